// round 3
// baseline (speedup 1.0000x reference)
#include <cuda_runtime.h>

namespace {

constexpr int NC  = 64;    // coarse samples
constexpr int NA  = 128;   // total samples in fine pass
constexpr int HID = 128;
constexpr int WPB = 8;     // warps (rays) per block

using u64 = unsigned long long;

__device__ __forceinline__ u64 f32x2_fma(u64 a, u64 b, u64 c) {
    u64 d;
    asm("fma.rn.f32x2 %0, %1, %2, %3;" : "=l"(d) : "l"(a), "l"(b), "l"(c));
    return d;
}
__device__ __forceinline__ u64 pack2(float lo, float hi) {
    u64 d;
    asm("mov.b64 %0, {%1, %2};" : "=l"(d) : "f"(lo), "f"(hi));
    return d;
}
__device__ __forceinline__ float2 unpack2(u64 v) {
    float2 r;
    asm("mov.b64 {%0, %1}, %2;" : "=f"(r.x), "=f"(r.y) : "l"(v));
    return r;
}

struct alignas(16) WarpSh {
    float4 abd[HID];        // (a, a, b, b) per hidden unit : 2048 B
    union {                 // lifetimes disjoint:
        float zsort[NA];    //   merged sorted z (after merge)
        float cdf[NA];      //   cdf[0..64] (before merge)
    };
    float kc[NC];           // coarse keys (sorted by construction)
    float kf[NC];           // fine keys
};                           // 3072 B

} // namespace

// Layer-2 weights + bias live in the constant bank (separate port from L1).
__constant__ float4 cW2c[HID];   // natural (wx, wy, wz, ww)
__constant__ float  cB2c[4];

namespace {

// MLP (layer1 collapsed to per-ray affine in z) + alpha compositing.
// P z-pairs => K = 2P samples per lane, lane-major, depth-sorted.
// Channel-major accumulators: axy = (r,g), azw = (b,sigma) per sample.
// Returns warp-summed (r, g, b, depth) on all lanes.
template <int P>
__device__ __forceinline__ float4 mlp_composite(
    const ulonglong2* __restrict__ abd,   // per-warp (aa, bb)
    u64 bxy, u64 bzw,
    const float* z, const float* delta, float* w_out, int lane)
{
    constexpr int K = 2 * P;
    u64 zz[P];
#pragma unroll
    for (int p = 0; p < P; p++) zz[p] = pack2(z[2 * p], z[2 * p + 1]);

    u64 axy[K], azw[K];
#pragma unroll
    for (int i = 0; i < K; i++) { axy[i] = bxy; azw[i] = bzw; }

#pragma unroll 8
    for (int j = 0; j < HID; j++) {
        ulonglong2 ab = abd[j];          // broadcast LDS.128 (only L1 traffic)
        float4 w = cW2c[j];              // constant port (LDCU), no L1
        u64 wxy = pack2(w.x, w.y);
        u64 wzw = pack2(w.z, w.w);
#pragma unroll
        for (int p = 0; p < P; p++) {
            u64 h2 = f32x2_fma(zz[p], ab.y, ab.x);
            float2 t = unpack2(h2);
            float h0 = fmaxf(t.x, 0.0f);
            float h1 = fmaxf(t.y, 0.0f);
            u64 h00 = pack2(h0, h0);
            u64 h11 = pack2(h1, h1);
            axy[2*p]   = f32x2_fma(h00, wxy, axy[2*p]);
            azw[2*p]   = f32x2_fma(h00, wzw, azw[2*p]);
            axy[2*p+1] = f32x2_fma(h11, wxy, axy[2*p+1]);
            azw[2*p+1] = f32x2_fma(h11, wzw, azw[2*p+1]);
        }
    }

    float rr[K], gg[K], bb[K], ss[K];
#pragma unroll
    for (int i = 0; i < K; i++) {
        float2 v0 = unpack2(axy[i]);
        float2 v1 = unpack2(azw[i]);
        rr[i] = v0.x; gg[i] = v0.y; bb[i] = v1.x; ss[i] = v1.y;
    }

    float alpha[K], f[K];
    float prod = 1.0f;
#pragma unroll
    for (int i = 0; i < K; i++) {
        float sig = fmaxf(ss[i], 0.0f);
        alpha[i] = 1.0f - __expf(-delta[i] * sig);
        f[i] = 1.0f - alpha[i] + 1e-10f;
        prod *= f[i];
    }

    // exclusive warp prefix-product of per-lane transmittance factors
    float sc = prod;
#pragma unroll
    for (int off = 1; off < 32; off <<= 1) {
        float v = __shfl_up_sync(0xffffffffu, sc, off);
        if (lane >= off) sc *= v;
    }
    float T = __shfl_up_sync(0xffffffffu, sc, 1);
    if (lane == 0) T = 1.0f;

    float rx = 0.f, ry = 0.f, rz = 0.f, dd = 0.f;
#pragma unroll
    for (int i = 0; i < K; i++) {
        float w = alpha[i] * T;
        if (w_out) w_out[i] = w;
        rx = fmaf(w, rr[i], rx);
        ry = fmaf(w, gg[i], ry);
        rz = fmaf(w, bb[i], rz);
        dd = fmaf(w, z[i],  dd);
        T *= f[i];
    }
#pragma unroll
    for (int off = 16; off > 0; off >>= 1) {
        rx += __shfl_xor_sync(0xffffffffu, rx, off);
        ry += __shfl_xor_sync(0xffffffffu, ry, off);
        rz += __shfl_xor_sync(0xffffffffu, rz, off);
        dd += __shfl_xor_sync(0xffffffffu, dd, off);
    }
    return make_float4(rx, ry, rz, dd);
}

} // namespace

__global__ void __launch_bounds__(WPB * 32, 4)
nerf_kernel(const float* __restrict__ rays,
            const float* __restrict__ u_coarse,
            const float* __restrict__ u_fine,
            const float* __restrict__ u_jitter,
            const float* __restrict__ W1,   // (3, 128)
            const float* __restrict__ b1,   // (128,)
            float* __restrict__ out)        // (R, 8)
{
    __shared__ WarpSh wsall[WPB];

    const int tid  = threadIdx.x;
    const int wid  = tid >> 5;
    const int lane = tid & 31;
    const int ray  = blockIdx.x * WPB + wid;

    WarpSh& ws = wsall[wid];
    const float* rp = rays + ray * 8;   // broadcast loads
    const float ox = rp[0], oy = rp[1], oz = rp[2];
    const float dx = rp[3], dy = rp[4], dz = rp[5];
    const float nearv = rp[6], farv = rp[7];
    const float zscale = (farv - nearv) * (1.0f / NC);   // z = near + key*zscale

    // Per-ray layer-1 affine coefficients: a = o@W1 + b1, b = d@W1
#pragma unroll
    for (int i = 0; i < 4; i++) {
        int j = lane + 32 * i;
        float w0 = W1[j], w1 = W1[HID + j], w2 = W1[2 * HID + j];
        float a  = fmaf(ox, w0, fmaf(oy, w1, fmaf(oz, w2, b1[j])));
        float bd = fmaf(dx, w0, fmaf(dy, w1, dz * w2));
        ws.abd[j] = make_float4(a, a, bd, bd);
    }
    __syncwarp();

    const u64 bxy = pack2(cB2c[0], cB2c[1]);
    const u64 bzw = pack2(cB2c[2], cB2c[3]);
    const ulonglong2* abd = reinterpret_cast<const ulonglong2*>(ws.abd);

    // ---------------- Coarse pass: keys 2*lane, 2*lane+1 ----------------
    float kc0, kc1, zc[2], dc[2];
    {
        float2 uc = reinterpret_cast<const float2*>(u_coarse + ray * NC)[lane];
        kc0 = (float)(2 * lane)     + uc.x;
        kc1 = (float)(2 * lane + 1) + uc.y;
        ws.kc[2 * lane]     = kc0;
        ws.kc[2 * lane + 1] = kc1;
        zc[0] = fmaf(kc0, zscale, nearv);
        zc[1] = fmaf(kc1, zscale, nearv);
        float znxt = __shfl_down_sync(0xffffffffu, zc[0], 1);
        if (lane == 31) znxt = farv;
        dc[0] = zc[1] - zc[0];
        dc[1] = znxt - zc[1];
    }
    float wgt[2];
    float4 coarse = mlp_composite<1>(abd, bxy, bzw, zc, dc, wgt, lane);

    // ---------------- PDF / CDF over coarse weights ----------------
    {
        float p0 = wgt[0] + 1e-5f;
        float p1 = wgt[1] + 1e-5f;
        float tot = p0 + p1;
#pragma unroll
        for (int off = 16; off > 0; off >>= 1)
            tot += __shfl_xor_sync(0xffffffffu, tot, off);
        float inv = 1.0f / tot;
        float pdf0 = p0 * inv, pdf1 = p1 * inv;
        float sc = pdf0 + pdf1;
#pragma unroll
        for (int off = 1; off < 32; off <<= 1) {
            float v = __shfl_up_sync(0xffffffffu, sc, off);
            if (lane >= off) sc += v;
        }
        float excl = __shfl_up_sync(0xffffffffu, sc, 1);
        if (lane == 0) excl = 0.0f;
        float c1 = excl + pdf0;
        if (lane == 0) ws.cdf[0] = 0.0f;
        ws.cdf[2 * lane + 1] = c1;
        ws.cdf[2 * lane + 2] = c1 + pdf1;
    }
    __syncwarp();

    // ------------- Fine sampling: searchsorted(right) - 1, + jitter -------------
    float kf0, kf1;
    int bin0, bin1;
    {
        float2 uf = reinterpret_cast<const float2*>(u_fine   + ray * NC)[lane];
        float2 uj = reinterpret_cast<const float2*>(u_jitter + ray * NC)[lane];
        float us[2] = {uf.x, uf.y};
        float js[2] = {uj.x, uj.y};
        int   bn[2];
        float kv[2];
#pragma unroll
        for (int k = 0; k < 2; k++) {
            int lo = 0, hi = 65;   // count of cdf entries <= u
            while (lo < hi) {
                int mid = (lo + hi) >> 1;
                if (ws.cdf[mid] <= us[k]) lo = mid + 1; else hi = mid;
            }
            int ind = max(lo - 1, 0);     // may be 64
            bn[k] = ind;
            kv[k] = (float)ind + js[k];   // key in [0, 65)
        }
        kf0 = kv[0]; kf1 = kv[1]; bin0 = bn[0]; bin1 = bn[1];
        ws.kf[2 * lane]     = kf0;
        ws.kf[2 * lane + 1] = kf1;
    }
    __syncwarp();   // cdf dead from here; its storage becomes zsort

    // ---------------- Merge by rank (key space, coarse pre-sorted) ----------------
    {
        int posc0 = 2 * lane;          // coarse rank among coarse = own index
        int posc1 = 2 * lane + 1;
        int posf0 = 0, posf1 = 0;      // fine rank among fine (tie by index)
        const int if0 = 2 * lane, if1 = 2 * lane + 1;
#pragma unroll 4
        for (int j = 0; j < NC; j++) {
            float q = ws.kf[j];        // broadcast
            posc0 += (q < kc0);
            posc1 += (q < kc1);
            posf0 += (q < kf0) || (q == kf0 && j < if0);
            posf1 += (q < kf1) || (q == kf1 && j < if1);
        }
        // coarse entries before each fine sample: bin + (kc[bin] <= kf)
        posf0 += (bin0 >= NC) ? NC : (bin0 + (ws.kc[bin0] <= kf0));
        posf1 += (bin1 >= NC) ? NC : (bin1 + (ws.kc[bin1] <= kf1));

        ws.zsort[posc0] = fmaf(kc0, zscale, nearv);
        ws.zsort[posc1] = fmaf(kc1, zscale, nearv);
        ws.zsort[posf0] = fmaf(kf0, zscale, nearv);
        ws.zsort[posf1] = fmaf(kf1, zscale, nearv);
    }
    __syncwarp();

    // ---------------- Fine pass: samples 4*lane .. 4*lane+3 ----------------
    float zf[4], df[4];
    {
        float4 zq = *reinterpret_cast<const float4*>(&ws.zsort[4 * lane]);
        zf[0] = zq.x; zf[1] = zq.y; zf[2] = zq.z; zf[3] = zq.w;
        float znxt = __shfl_down_sync(0xffffffffu, zq.x, 1);
        if (lane == 31) znxt = farv;
        df[0] = zf[1] - zf[0];
        df[1] = zf[2] - zf[1];
        df[2] = zf[3] - zf[2];
        df[3] = znxt - zf[3];
    }
    float4 fine = mlp_composite<2>(abd, bxy, bzw, zf, df, nullptr, lane);

    if (lane == 0) {
        float4* op = reinterpret_cast<float4*>(out + ray * 8);
        op[0] = make_float4(coarse.x, coarse.y, coarse.z, coarse.w);
        op[1] = make_float4(fine.x, fine.y, fine.z, fine.w);
    }
}

extern "C" void kernel_launch(void* const* d_in, const int* in_sizes, int n_in,
                              void* d_out, int out_size)
{
    const float* rays     = (const float*)d_in[0];
    const float* u_coarse = (const float*)d_in[1];
    const float* u_fine   = (const float*)d_in[2];
    const float* u_jitter = (const float*)d_in[3];
    const float* W1       = (const float*)d_in[4];
    const float* b1       = (const float*)d_in[5];
    const float* W2       = (const float*)d_in[6];
    const float* b2       = (const float*)d_in[7];
    float* out            = (float*)d_out;

    static bool carveout_set = false;
    if (!carveout_set) {
        cudaFuncSetAttribute(nerf_kernel,
                             cudaFuncAttributePreferredSharedMemoryCarveout,
                             cudaSharedmemCarveoutMaxShared);
        carveout_set = true;
    }

    // Stage layer-2 weights into the constant bank (D2D async: capturable).
    cudaMemcpyToSymbolAsync(cW2c, W2, HID * sizeof(float4), 0,
                            cudaMemcpyDeviceToDevice, 0);
    cudaMemcpyToSymbolAsync(cB2c, b2, 4 * sizeof(float), 0,
                            cudaMemcpyDeviceToDevice, 0);

    const int R = in_sizes[0] / 8;          // 16384
    const int blocks = R / WPB;             // 2048
    nerf_kernel<<<blocks, WPB * 32>>>(rays, u_coarse, u_fine, u_jitter,
                                      W1, b1, out);
}

// round 4
// speedup vs baseline: 1.7046x; 1.7046x over previous
#include <cuda_runtime.h>

namespace {

constexpr int NC  = 64;    // coarse samples
constexpr int NA  = 128;   // total samples in fine pass
constexpr int HID = 128;
constexpr int WPB = 4;     // warps (rays) per block

using u64 = unsigned long long;

__device__ __forceinline__ u64 f32x2_fma(u64 a, u64 b, u64 c) {
    u64 d;
    asm("fma.rn.f32x2 %0, %1, %2, %3;" : "=l"(d) : "l"(a), "l"(b), "l"(c));
    return d;
}
__device__ __forceinline__ u64 pack2(float lo, float hi) {
    u64 d;
    asm("mov.b64 %0, {%1, %2};" : "=l"(d) : "f"(lo), "f"(hi));
    return d;
}
__device__ __forceinline__ float2 unpack2(u64 v) {
    float2 r;
    asm("mov.b64 {%0, %1}, %2;" : "=f"(r.x), "=f"(r.y) : "l"(v));
    return r;
}

struct alignas(16) WarpSh {
    float4 abd[HID];            // (a, a, b, b) per hidden unit : 2048 B
    union {                     // lifetimes disjoint:
        float cdf[68];          //   cdf[0..64]  (pdf->sampling)
        struct {
            float  zs[NA];      //   sorted z            : 512 B
            float4 outs[NA];    //   sorted (r,g,b,sig)   : 2048 B
        } m;                    //   (merge->fine composite)
    } u;
    float kc[NC];               // coarse keys (sorted by construction)
    float kf[NC];               // fine keys
};                              // 5120 B

// MLP for 2 samples (layer1 collapsed to per-ray affine in z).
// Natural W2 layout; channel-major packed accumulators.
__device__ __forceinline__ void mlp2(
    const ulonglong2* __restrict__ abd,   // per-warp (aa, bb)
    const float4* __restrict__ W2s,       // (wx, wy, wz, ww)
    u64 bxy, u64 bzw,
    float z0, float z1, float4& o0, float4& o1)
{
    const u64 zz = pack2(z0, z1);
    u64 a0xy = bxy, a0zw = bzw, a1xy = bxy, a1zw = bzw;

#pragma unroll 8
    for (int j = 0; j < HID; j++) {
        ulonglong2 ab = abd[j];          // broadcast LDS.128
        float4 w = W2s[j];               // broadcast LDS.128
        u64 wxy = pack2(w.x, w.y);
        u64 wzw = pack2(w.z, w.w);
        u64 h2 = f32x2_fma(zz, ab.y, ab.x);
        float2 t = unpack2(h2);
        float h0 = fmaxf(t.x, 0.0f);
        float h1 = fmaxf(t.y, 0.0f);
        u64 h00 = pack2(h0, h0);
        u64 h11 = pack2(h1, h1);
        a0xy = f32x2_fma(h00, wxy, a0xy);
        a0zw = f32x2_fma(h00, wzw, a0zw);
        a1xy = f32x2_fma(h11, wxy, a1xy);
        a1zw = f32x2_fma(h11, wzw, a1zw);
    }
    float2 v;
    v = unpack2(a0xy); o0.x = v.x; o0.y = v.y;
    v = unpack2(a0zw); o0.z = v.x; o0.w = v.y;
    v = unpack2(a1xy); o1.x = v.x; o1.y = v.y;
    v = unpack2(a1zw); o1.z = v.x; o1.w = v.y;
}

// Alpha compositing over K depth-sorted samples/lane (lane-major order).
// o[i] = (r, g, b, sigma). Returns warp-summed (r, g, b, depth) on all lanes.
template <int K>
__device__ __forceinline__ float4 composite(
    const float4* o, const float* z, const float* delta, float* w_out, int lane)
{
    float alpha[K], f[K];
    float prod = 1.0f;
#pragma unroll
    for (int i = 0; i < K; i++) {
        float sig = fmaxf(o[i].w, 0.0f);
        alpha[i] = 1.0f - __expf(-delta[i] * sig);
        f[i] = 1.0f - alpha[i] + 1e-10f;
        prod *= f[i];
    }

    // exclusive warp prefix-product of per-lane transmittance factors
    float sc = prod;
#pragma unroll
    for (int off = 1; off < 32; off <<= 1) {
        float v = __shfl_up_sync(0xffffffffu, sc, off);
        if (lane >= off) sc *= v;
    }
    float T = __shfl_up_sync(0xffffffffu, sc, 1);
    if (lane == 0) T = 1.0f;

    float rx = 0.f, ry = 0.f, rz = 0.f, dd = 0.f;
#pragma unroll
    for (int i = 0; i < K; i++) {
        float w = alpha[i] * T;
        if (w_out) w_out[i] = w;
        rx = fmaf(w, o[i].x, rx);
        ry = fmaf(w, o[i].y, ry);
        rz = fmaf(w, o[i].z, rz);
        dd = fmaf(w, z[i],   dd);
        T *= f[i];
    }
#pragma unroll
    for (int off = 16; off > 0; off >>= 1) {
        rx += __shfl_xor_sync(0xffffffffu, rx, off);
        ry += __shfl_xor_sync(0xffffffffu, ry, off);
        rz += __shfl_xor_sync(0xffffffffu, rz, off);
        dd += __shfl_xor_sync(0xffffffffu, dd, off);
    }
    return make_float4(rx, ry, rz, dd);
}

} // namespace

__global__ void __launch_bounds__(WPB * 32)
nerf_kernel(const float* __restrict__ rays,
            const float* __restrict__ u_coarse,
            const float* __restrict__ u_fine,
            const float* __restrict__ u_jitter,
            const float* __restrict__ W1,   // (3, 128)
            const float* __restrict__ b1,   // (128,)
            const float* __restrict__ W2,   // (128, 4)
            const float* __restrict__ b2,   // (4,)
            float* __restrict__ out)        // (R, 8)
{
    __shared__ float4 W2s[HID];
    __shared__ float4 b2s;
    __shared__ WarpSh wsall[WPB];

    const int tid  = threadIdx.x;
    const int wid  = tid >> 5;
    const int lane = tid & 31;
    const int ray  = blockIdx.x * WPB + wid;

    W2s[tid] = reinterpret_cast<const float4*>(W2)[tid];   // blockDim == 128
    if (tid == 0) b2s = *reinterpret_cast<const float4*>(b2);
    __syncthreads();

    WarpSh& ws = wsall[wid];
    const float* rp = rays + ray * 8;   // broadcast loads
    const float ox = rp[0], oy = rp[1], oz = rp[2];
    const float dx = rp[3], dy = rp[4], dz = rp[5];
    const float nearv = rp[6], farv = rp[7];
    const float zscale = (farv - nearv) * (1.0f / NC);   // z = near + key*zscale

    // Per-ray layer-1 affine coefficients: a = o@W1 + b1, b = d@W1
#pragma unroll
    for (int i = 0; i < 4; i++) {
        int j = lane + 32 * i;
        float w0 = W1[j], w1 = W1[HID + j], w2 = W1[2 * HID + j];
        float a  = fmaf(ox, w0, fmaf(oy, w1, fmaf(oz, w2, b1[j])));
        float bd = fmaf(dx, w0, fmaf(dy, w1, dz * w2));
        ws.abd[j] = make_float4(a, a, bd, bd);
    }
    __syncwarp();

    const float4 b2v = b2s;
    const u64 bxy = pack2(b2v.x, b2v.y);
    const u64 bzw = pack2(b2v.z, b2v.w);
    const ulonglong2* abd = reinterpret_cast<const ulonglong2*>(ws.abd);

    // ---------------- Coarse pass: keys 2*lane, 2*lane+1 ----------------
    float kc0, kc1;
    float zca[2], dca[2];
    {
        float2 uc = reinterpret_cast<const float2*>(u_coarse + ray * NC)[lane];
        kc0 = (float)(2 * lane)     + uc.x;
        kc1 = (float)(2 * lane + 1) + uc.y;
        ws.kc[2 * lane]     = kc0;
        ws.kc[2 * lane + 1] = kc1;
        zca[0] = fmaf(kc0, zscale, nearv);
        zca[1] = fmaf(kc1, zscale, nearv);
        float znxt = __shfl_down_sync(0xffffffffu, zca[0], 1);
        if (lane == 31) znxt = farv;
        dca[0] = zca[1] - zca[0];
        dca[1] = znxt - zca[1];
    }
    float4 co[2];
    mlp2(abd, W2s, bxy, bzw, zca[0], zca[1], co[0], co[1]);

    float wgt[2];
    float4 coarse = composite<2>(co, zca, dca, wgt, lane);

    // ---------------- PDF / CDF over coarse weights ----------------
    {
        float p0 = wgt[0] + 1e-5f;
        float p1 = wgt[1] + 1e-5f;
        float tot = p0 + p1;
#pragma unroll
        for (int off = 16; off > 0; off >>= 1)
            tot += __shfl_xor_sync(0xffffffffu, tot, off);
        float inv = 1.0f / tot;
        float pdf0 = p0 * inv, pdf1 = p1 * inv;
        float sc = pdf0 + pdf1;
#pragma unroll
        for (int off = 1; off < 32; off <<= 1) {
            float v = __shfl_up_sync(0xffffffffu, sc, off);
            if (lane >= off) sc += v;
        }
        float excl = __shfl_up_sync(0xffffffffu, sc, 1);
        if (lane == 0) excl = 0.0f;
        float c1 = excl + pdf0;
        if (lane == 0) ws.u.cdf[0] = 0.0f;
        ws.u.cdf[2 * lane + 1] = c1;
        ws.u.cdf[2 * lane + 2] = c1 + pdf1;
    }
    __syncwarp();

    // ------------- Fine sampling: searchsorted(right) - 1, + jitter -------------
    float kf0, kf1;
    int bin0, bin1;
    {
        float2 uf = reinterpret_cast<const float2*>(u_fine   + ray * NC)[lane];
        float2 uj = reinterpret_cast<const float2*>(u_jitter + ray * NC)[lane];
        float us[2] = {uf.x, uf.y};
        float js[2] = {uj.x, uj.y};
        int   bn[2];
        float kv[2];
#pragma unroll
        for (int k = 0; k < 2; k++) {
            int lo = 0, hi = 65;   // count of cdf entries <= u
            while (lo < hi) {
                int mid = (lo + hi) >> 1;
                if (ws.u.cdf[mid] <= us[k]) lo = mid + 1; else hi = mid;
            }
            int ind = max(lo - 1, 0);     // may be 64
            bn[k] = ind;
            kv[k] = (float)ind + js[k];   // key in [0, 65)
        }
        kf0 = kv[0]; kf1 = kv[1]; bin0 = bn[0]; bin1 = bn[1];
        ws.kf[2 * lane]     = kf0;
        ws.kf[2 * lane + 1] = kf1;
    }
    __syncwarp();   // cdf dead from here; storage becomes zs/outs

    // ---------------- MLP on the 64 NEW fine samples only ----------------
    const float zn0 = fmaf(kf0, zscale, nearv);
    const float zn1 = fmaf(kf1, zscale, nearv);
    float4 fo[2];
    mlp2(abd, W2s, bxy, bzw, zn0, zn1, fo[0], fo[1]);

    // ---------------- Merge by rank (key space, coarse pre-sorted) ----------------
    {
        int posc0 = 2 * lane;          // coarse rank among coarse = own index
        int posc1 = 2 * lane + 1;
        int posf0 = 0, posf1 = 0;      // fine rank among fine (tie by index)
        const int if0 = 2 * lane, if1 = 2 * lane + 1;
#pragma unroll 4
        for (int j = 0; j < NC; j++) {
            float q = ws.kf[j];        // broadcast
            posc0 += (q < kc0);
            posc1 += (q < kc1);
            posf0 += (q < kf0) || (q == kf0 && j < if0);
            posf1 += (q < kf1) || (q == kf1 && j < if1);
        }
        // coarse entries before each fine sample: bin + (kc[bin] <= kf)
        posf0 += (bin0 >= NC) ? NC : (bin0 + (ws.kc[bin0] <= kf0));
        posf1 += (bin1 >= NC) ? NC : (bin1 + (ws.kc[bin1] <= kf1));

        // scatter (z, MLP out) records into sorted order
        ws.u.m.zs[posc0] = zca[0];  ws.u.m.outs[posc0] = co[0];
        ws.u.m.zs[posc1] = zca[1];  ws.u.m.outs[posc1] = co[1];
        ws.u.m.zs[posf0] = zn0;     ws.u.m.outs[posf0] = fo[0];
        ws.u.m.zs[posf1] = zn1;     ws.u.m.outs[posf1] = fo[1];
    }
    __syncwarp();

    // ---------------- Fine composite: samples 4*lane .. 4*lane+3 ----------------
    float zf[4], df[4];
    float4 go[4];
    {
        float4 zq = *reinterpret_cast<const float4*>(&ws.u.m.zs[4 * lane]);
        zf[0] = zq.x; zf[1] = zq.y; zf[2] = zq.z; zf[3] = zq.w;
#pragma unroll
        for (int i = 0; i < 4; i++) go[i] = ws.u.m.outs[4 * lane + i];
        float znxt = __shfl_down_sync(0xffffffffu, zq.x, 1);
        if (lane == 31) znxt = farv;
        df[0] = zf[1] - zf[0];
        df[1] = zf[2] - zf[1];
        df[2] = zf[3] - zf[2];
        df[3] = znxt - zf[3];
    }
    float4 fine = composite<4>(go, zf, df, nullptr, lane);

    if (lane == 0) {
        float4* op = reinterpret_cast<float4*>(out + ray * 8);
        op[0] = make_float4(coarse.x, coarse.y, coarse.z, coarse.w);
        op[1] = make_float4(fine.x, fine.y, fine.z, fine.w);
    }
}

extern "C" void kernel_launch(void* const* d_in, const int* in_sizes, int n_in,
                              void* d_out, int out_size)
{
    const float* rays     = (const float*)d_in[0];
    const float* u_coarse = (const float*)d_in[1];
    const float* u_fine   = (const float*)d_in[2];
    const float* u_jitter = (const float*)d_in[3];
    const float* W1       = (const float*)d_in[4];
    const float* b1       = (const float*)d_in[5];
    const float* W2       = (const float*)d_in[6];
    const float* b2       = (const float*)d_in[7];
    float* out            = (float*)d_out;

    static bool carveout_set = false;
    if (!carveout_set) {
        cudaFuncSetAttribute(nerf_kernel,
                             cudaFuncAttributePreferredSharedMemoryCarveout,
                             cudaSharedmemCarveoutMaxShared);
        carveout_set = true;
    }

    const int R = in_sizes[0] / 8;          // 16384
    const int blocks = R / WPB;             // 4096
    nerf_kernel<<<blocks, WPB * 32>>>(rays, u_coarse, u_fine, u_jitter,
                                      W1, b1, W2, b2, out);
}